// round 6
// baseline (speedup 1.0000x reference)
#include <cuda_runtime.h>

// R2Ntab: out[b] = (# rules r with h[b,r] > 0.999999) * [w_or>0] + b_or,
// h[b,r] = x_b . rw_r + b_and[r] - relu(rw_r).sum(), rw = w_and masked by
// w_cancel<0 columns. x binary {0,1} => pass <=> deficit(sum |w| over
// mismatched care features) < eps_r = b_and[r]-0.999999, which for
// |w| >= eps on all care features is EXACTLY the 256-bit pattern match
// (x_bits & care_r) == pos_r. Tiny weights -> don't-care if their total
// < eps, else that rule takes an exact fp32-dot fallback (expected: none).
//
// R6: single fused kernel. Each block builds the 4KB rule-mask table itself
// (Phase A, ~1us, wa is L2-resident after wave 1), then streams rows with
// the R3-winning register-MLP=8 loop (Phase B). Removes the separate prep
// kernel + one graph-node launch (~5us of fixed overhead).

#define FDIM 256
#define RDIM 128
#define UNROLL 4
#define NTHREADS 256
#define NBLOCKS 592

// Bit layout: feature f = h*128 + 4*j + c -> word w = h*4 + c, bit j.

// x entries are exactly 0.0f / 1.0f -> exact integer pack via FFMA chain.
__device__ __forceinline__ unsigned pack_bits(float4 a, float4 b) {
    float s = a.x;
    s = fmaf(2.f,   a.y, s);
    s = fmaf(4.f,   a.z, s);
    s = fmaf(8.f,   a.w, s);
    s = fmaf(16.f,  b.x, s);
    s = fmaf(32.f,  b.y, s);
    s = fmaf(64.f,  b.z, s);
    s = fmaf(128.f, b.w, s);
    return (unsigned)s;
}

__global__ void __launch_bounds__(NTHREADS, 4)
fused_kernel(const float* __restrict__ x,
             const float* __restrict__ wc,
             const float* __restrict__ wa,
             const float* __restrict__ ba,
             const float* __restrict__ wo,
             const float* __restrict__ bor,
             float* __restrict__ out, int B) {
    __shared__ unsigned s_pos[8][RDIM];
    __shared__ unsigned s_care[8][RDIM];
    __shared__ float    s_thresh[RDIM];
    __shared__ int      s_nx;
    __shared__ int      s_xr[RDIM];

    const int tid  = threadIdx.x;
    const int lane = tid & 31;
    const int wid  = tid >> 5;

    if (tid == 0) s_nx = 0;
    __syncthreads();

    // ---------------- Phase A: build rule masks (warp per rule, 16 each) ----
    for (int r = wid; r < RDIM; r += 8) {
        float eps     = ba[r] - 0.999999f;
        bool  include = wo[r] > 0.0f;

        float relu_sum = 0.f, sum_tiny = 0.f;
        unsigned pos[8], care[8];
#pragma unroll
        for (int h = 0; h < 2; h++) {
            float4 w4 = *(const float4*)(wa + r * FDIM + h * 128 + 4 * lane);
            float4 m4 = *(const float4*)(wc + h * 128 + 4 * lane);
            float wv[4];
            wv[0] = (m4.x < 0.f) ? 0.f : w4.x;
            wv[1] = (m4.y < 0.f) ? 0.f : w4.y;
            wv[2] = (m4.z < 0.f) ? 0.f : w4.z;
            wv[3] = (m4.w < 0.f) ? 0.f : w4.w;
#pragma unroll
            for (int c = 0; c < 4; c++) {
                int w = h * 4 + c;
                relu_sum += fmaxf(wv[c], 0.f);
                float aw   = fabsf(wv[c]);
                bool  must = (aw >= eps);
                if (!must) sum_tiny += aw;
                pos[w]  = __ballot_sync(0xffffffffu, must && (wv[c] > 0.f));
                care[w] = __ballot_sync(0xffffffffu, must && (wv[c] != 0.f));
            }
        }
#pragma unroll
        for (int o = 16; o; o >>= 1) {
            relu_sum += __shfl_xor_sync(0xffffffffu, relu_sum, o);
            sum_tiny += __shfl_xor_sync(0xffffffffu, sum_tiny, o);
        }

        bool afalse = (!include) || (eps <= 0.f);
        bool exact  = (!afalse) && (sum_tiny >= eps);
        if (afalse || exact) {
#pragma unroll
            for (int w = 0; w < 8; w++) { pos[w] = 0u; care[w] = 0u; }
            pos[0] = 0xFFFFFFFFu;   // (x & 0) == 0xFFFFFFFF: never matches
        }
        if (lane == 0) {
            s_thresh[r] = relu_sum - eps;
            if (exact) {
                int i = atomicAdd(&s_nx, 1);
                s_xr[i] = r;
            }
#pragma unroll
            for (int w = 0; w < 8; w++) { s_pos[w][r] = pos[w]; s_care[w][r] = care[w]; }
        }
    }
    __syncthreads();

    // ---------------- Phase B: stream rows (warp per row, MLP = 8) ---------
    const int   nx = s_nx;
    const float b0 = bor[0];

    // Word-0 masks for this lane's 4 rules, register-resident.
    unsigned p0[4], c0[4];
#pragma unroll
    for (int k = 0; k < 4; k++) {
        p0[k] = s_pos[0][lane + 32 * k];
        c0[k] = s_care[0][lane + 32 * k];
    }

    const int gw = blockIdx.x * (NTHREADS >> 5) + wid;
    const int nw = gridDim.x * (NTHREADS >> 5);
    const int nchunks = B / UNROLL;

    for (int ch = gw; ch < nchunks; ch += nw) {
        int row0 = ch * UNROLL;

        // Issue all 8 loads up front (independent -> MLP = 8).
        float4 a[UNROLL], b[UNROLL];
#pragma unroll
        for (int u = 0; u < UNROLL; u++) {
            const float4* xr = (const float4*)(x + (size_t)(row0 + u) * FDIM);
            a[u] = __ldcs(&xr[lane]);
            b[u] = __ldcs(&xr[lane + 32]);
        }

        unsigned bits[UNROLL];
#pragma unroll
        for (int u = 0; u < UNROLL; u++)
            bits[u] = pack_bits(a[u], b[u]);

#pragma unroll
        for (int u = 0; u < UNROLL; u++) {
            unsigned xw0 = __ballot_sync(0xffffffffu, bits[u] & 1u);
            bool cand = false;
#pragma unroll
            for (int k = 0; k < 4; k++)
                cand |= (((xw0 & c0[k]) ^ p0[k]) == 0u);
            unsigned any = __ballot_sync(0xffffffffu, cand);

            if (any == 0u && nx == 0) {              // warp-uniform, ~always
                if (lane == 0) out[row0 + u] = b0;
                continue;
            }

            // Rare path: remaining 7 ballots + full 256-bit checks.
            unsigned xw[8];
            xw[0] = xw0;
#pragma unroll
            for (int w = 1; w < 8; w++)
                xw[w] = __ballot_sync(0xffffffffu, (bits[u] >> w) & 1u);

            int cnt = 0;
#pragma unroll
            for (int k = 0; k < 4; k++) {
                int r = lane + 32 * k;
                unsigned acc = (xw0 & c0[k]) ^ p0[k];
                if (acc == 0u) {
#pragma unroll
                    for (int w = 1; w < 8; w++)
                        acc |= (xw[w] & s_care[w][r]) ^ s_pos[w][r];
                    if (acc == 0u) cnt++;
                }
            }
            // Exact fp32 fallback (expected nx == 0); rw recomputed on demand.
            for (int e = 0; e < nx; e++) {
                int r = s_xr[e];
                float s = 0.f;
#pragma unroll
                for (int w = 0; w < 8; w++) {
                    if ((xw[w] >> lane) & 1u) {
                        int f = (w >> 2) * 128 + 4 * lane + (w & 3);
                        float wv = (wc[f] < 0.f) ? 0.f : wa[r * FDIM + f];
                        s += wv;
                    }
                }
#pragma unroll
                for (int o = 16; o; o >>= 1)
                    s += __shfl_xor_sync(0xffffffffu, s, o);
                if (lane == 0 && s > s_thresh[r]) cnt++;
            }
#pragma unroll
            for (int o = 16; o; o >>= 1)
                cnt += __shfl_xor_sync(0xffffffffu, cnt, o);
            if (lane == 0) out[row0 + u] = (float)cnt + b0;
        }
    }

    // Tail rows (B not divisible by UNROLL; not hit for B = 131072).
    for (int row = nchunks * UNROLL + gw; row < B; row += nw) {
        const float4* xr = (const float4*)(x + (size_t)row * FDIM);
        float4 a = __ldcs(&xr[lane]);
        float4 b = __ldcs(&xr[lane + 32]);
        unsigned bits = pack_bits(a, b);
        unsigned xw[8];
#pragma unroll
        for (int w = 0; w < 8; w++)
            xw[w] = __ballot_sync(0xffffffffu, (bits >> w) & 1u);
        int cnt = 0;
#pragma unroll
        for (int k = 0; k < 4; k++) {
            int r = lane + 32 * k;
            unsigned acc = 0u;
#pragma unroll
            for (int w = 0; w < 8; w++)
                acc |= (xw[w] & s_care[w][r]) ^ s_pos[w][r];
            if (acc == 0u) cnt++;
        }
        for (int e = 0; e < nx; e++) {
            int r = s_xr[e];
            float s = 0.f;
#pragma unroll
            for (int w = 0; w < 8; w++) {
                if ((xw[w] >> lane) & 1u) {
                    int f = (w >> 2) * 128 + 4 * lane + (w & 3);
                    float wv = (wc[f] < 0.f) ? 0.f : wa[r * FDIM + f];
                    s += wv;
                }
            }
#pragma unroll
            for (int o = 16; o; o >>= 1)
                s += __shfl_xor_sync(0xffffffffu, s, o);
            if (lane == 0 && s > s_thresh[r]) cnt++;
        }
#pragma unroll
        for (int o = 16; o; o >>= 1)
            cnt += __shfl_xor_sync(0xffffffffu, cnt, o);
        if (lane == 0) out[row] = (float)cnt + b0;
    }
}

extern "C" void kernel_launch(void* const* d_in, const int* in_sizes, int n_in,
                              void* d_out, int out_size) {
    const float* x  = (const float*)d_in[0];   // [B, 256] binary
    const float* wc = (const float*)d_in[1];   // [256]
    const float* wa = (const float*)d_in[2];   // [128, 256]
    const float* ba = (const float*)d_in[3];   // [128]
    const float* wo = (const float*)d_in[4];   // [1, 128]
    const float* bo = (const float*)d_in[5];   // [1]
    float* out = (float*)d_out;

    int B = in_sizes[0] / FDIM;

    fused_kernel<<<NBLOCKS, NTHREADS>>>(x, wc, wa, ba, wo, bo, out, B);
}

// round 7
// speedup vs baseline: 1.3272x; 1.3272x over previous
#include <cuda_runtime.h>

// R2Ntab: out[b] = (# rules r with h[b,r] > 0.999999) * [w_or>0] + b_or,
// h[b,r] = x_b . rw_r + b_and[r] - relu(rw_r).sum(), rw = w_and masked by
// w_cancel<0 columns. x binary {0,1} => pass <=> deficit(sum |w| over
// mismatched care features) < eps_r = b_and[r]-0.999999, which when
// |w| >= eps on all care features is EXACTLY the 256-bit pattern match
// (x_bits & care_r) == pos_r. Tiny weights -> don't-care if their total
// < eps, else that rule takes an exact fp32-dot fallback (expected: none).
//
// R7: two-kernel structure (R3, best at 31.2us) + the fast-path upgrades
// that were never tested inside it: FFMA bit-pack (halves alu work) and
// 2-ballot fast path (8 ballots -> 2 on the ~always path).

#define FDIM 256
#define RDIM 128
#define UNROLL 4
#define NTHREADS 256
#define NBLOCKS 592

// Bit layout: feature f = h*128 + 4*j + c -> word w = h*4 + c, bit j.

__device__ unsigned g_pos[8][RDIM];
__device__ unsigned g_care[8][RDIM];
__device__ float    g_thresh[RDIM];
__device__ float    g_rw[RDIM * FDIM];
__device__ int      g_exact_flag[RDIM];

// ---------------------------------------------------------------------------
// Prep: one warp per rule (vectorized loads).
// ---------------------------------------------------------------------------
__global__ void prep_kernel(const float* __restrict__ wc,
                            const float* __restrict__ wa,
                            const float* __restrict__ ba,
                            const float* __restrict__ wo) {
    int gt   = blockIdx.x * blockDim.x + threadIdx.x;
    int r    = gt >> 5;
    int lane = gt & 31;
    if (r >= RDIM) return;

    float eps     = ba[r] - 0.999999f;
    bool  include = wo[r] > 0.0f;

    float relu_sum = 0.f, sum_tiny = 0.f;
    unsigned pos[8], care[8];
#pragma unroll
    for (int h = 0; h < 2; h++) {
        float4 w4 = *(const float4*)(wa + r * FDIM + h * 128 + 4 * lane);
        float4 m4 = *(const float4*)(wc + h * 128 + 4 * lane);
        float wv[4];
        wv[0] = (m4.x < 0.f) ? 0.f : w4.x;
        wv[1] = (m4.y < 0.f) ? 0.f : w4.y;
        wv[2] = (m4.z < 0.f) ? 0.f : w4.z;
        wv[3] = (m4.w < 0.f) ? 0.f : w4.w;
#pragma unroll
        for (int c = 0; c < 4; c++) {
            int w = h * 4 + c;
            int f = h * 128 + 4 * lane + c;
            g_rw[r * FDIM + f] = wv[c];
            relu_sum += fmaxf(wv[c], 0.f);
            float aw   = fabsf(wv[c]);
            bool  must = (aw >= eps);
            if (!must) sum_tiny += aw;
            pos[w]  = __ballot_sync(0xffffffffu, must && (wv[c] > 0.f));
            care[w] = __ballot_sync(0xffffffffu, must && (wv[c] != 0.f));
        }
    }
#pragma unroll
    for (int o = 16; o; o >>= 1) {
        relu_sum += __shfl_xor_sync(0xffffffffu, relu_sum, o);
        sum_tiny += __shfl_xor_sync(0xffffffffu, sum_tiny, o);
    }

    bool afalse = (!include) || (eps <= 0.f);
    bool exact  = (!afalse) && (sum_tiny >= eps);
    if (afalse || exact) {
#pragma unroll
        for (int w = 0; w < 8; w++) { pos[w] = 0u; care[w] = 0u; }
        pos[0] = 0xFFFFFFFFu;   // (x & 0) == 0xFFFFFFFF: never matches
    }
    if (lane == 0) {
        g_thresh[r]     = relu_sum - eps;
        g_exact_flag[r] = exact ? 1 : 0;
#pragma unroll
        for (int w = 0; w < 8; w++) { g_pos[w][r] = pos[w]; g_care[w][r] = care[w]; }
    }
}

// x entries are exactly 0.0f / 1.0f -> exact integer pack via FFMA chain.
__device__ __forceinline__ unsigned pack_bits(float4 a, float4 b) {
    float s = a.x;
    s = fmaf(2.f,   a.y, s);
    s = fmaf(4.f,   a.z, s);
    s = fmaf(8.f,   a.w, s);
    s = fmaf(16.f,  b.x, s);
    s = fmaf(32.f,  b.y, s);
    s = fmaf(64.f,  b.z, s);
    s = fmaf(128.f, b.w, s);
    return (unsigned)s;
}

// ---------------------------------------------------------------------------
// Main: warp per row, UNROLL=4 rows per chunk, 8 LDG.128 issued up front
// (MLP=8). Fast path per row: FFMA pack + 2 ballots + 4 LOP3/ISETP.
// ---------------------------------------------------------------------------
__global__ void __launch_bounds__(NTHREADS, 4)
main_kernel(const float* __restrict__ x,
            const float* __restrict__ bor,
            float* __restrict__ out, int B) {
    __shared__ unsigned s_pos[8][RDIM];
    __shared__ unsigned s_care[8][RDIM];
    __shared__ int s_nx;
    __shared__ int s_xr[RDIM];

    const int tid = threadIdx.x;
    if (tid == 0) s_nx = 0;
    __syncthreads();
    for (int i = tid; i < 8 * RDIM; i += NTHREADS) {
        (&s_pos[0][0])[i]  = (&g_pos[0][0])[i];
        (&s_care[0][0])[i] = (&g_care[0][0])[i];
    }
    if (tid < RDIM && g_exact_flag[tid]) {
        int i = atomicAdd(&s_nx, 1);
        s_xr[i] = tid;
    }
    __syncthreads();

    const int   lane = tid & 31;
    const int   nx   = s_nx;
    const float b0   = bor[0];

    // Word-0 masks for this lane's 4 rules, register-resident.
    unsigned p0[4], c0[4];
#pragma unroll
    for (int k = 0; k < 4; k++) {
        p0[k] = s_pos[0][lane + 32 * k];
        c0[k] = s_care[0][lane + 32 * k];
    }

    const int gw = blockIdx.x * (NTHREADS >> 5) + (tid >> 5);
    const int nw = gridDim.x * (NTHREADS >> 5);
    const int nchunks = B / UNROLL;

    for (int ch = gw; ch < nchunks; ch += nw) {
        int row0 = ch * UNROLL;

        // Issue all 8 loads up front (independent -> MLP = 8), then pack
        // immediately so the float4s die fast (register pressure).
        unsigned bits[UNROLL];
        {
            float4 a[UNROLL], b[UNROLL];
#pragma unroll
            for (int u = 0; u < UNROLL; u++) {
                const float4* xr = (const float4*)(x + (size_t)(row0 + u) * FDIM);
                a[u] = __ldcs(&xr[lane]);
                b[u] = __ldcs(&xr[lane + 32]);
            }
#pragma unroll
            for (int u = 0; u < UNROLL; u++)
                bits[u] = pack_bits(a[u], b[u]);
        }

#pragma unroll
        for (int u = 0; u < UNROLL; u++) {
            unsigned xw0 = __ballot_sync(0xffffffffu, bits[u] & 1u);
            bool cand = false;
#pragma unroll
            for (int k = 0; k < 4; k++)
                cand |= (((xw0 & c0[k]) ^ p0[k]) == 0u);
            unsigned any = __ballot_sync(0xffffffffu, cand);

            if (any == 0u && nx == 0) {              // warp-uniform, ~always
                if (lane == 0) out[row0 + u] = b0;
                continue;
            }

            // Rare path: remaining 7 ballots + full 256-bit checks.
            unsigned xw[8];
            xw[0] = xw0;
#pragma unroll
            for (int w = 1; w < 8; w++)
                xw[w] = __ballot_sync(0xffffffffu, (bits[u] >> w) & 1u);

            int cnt = 0;
#pragma unroll
            for (int k = 0; k < 4; k++) {
                int r = lane + 32 * k;
                unsigned acc = (xw0 & c0[k]) ^ p0[k];
                if (acc == 0u) {
#pragma unroll
                    for (int w = 1; w < 8; w++)
                        acc |= (xw[w] & s_care[w][r]) ^ s_pos[w][r];
                    if (acc == 0u) cnt++;
                }
            }
            // Exact fp32 fallback for flagged rules (expected nx == 0).
            for (int e = 0; e < nx; e++) {
                int r = s_xr[e];
                float s = 0.f;
#pragma unroll
                for (int w = 0; w < 8; w++) {
                    if ((xw[w] >> lane) & 1u) {
                        int f = (w >> 2) * 128 + 4 * lane + (w & 3);
                        s += g_rw[r * FDIM + f];
                    }
                }
#pragma unroll
                for (int o = 16; o; o >>= 1)
                    s += __shfl_xor_sync(0xffffffffu, s, o);
                if (lane == 0 && s > g_thresh[r]) cnt++;
            }
#pragma unroll
            for (int o = 16; o; o >>= 1)
                cnt += __shfl_xor_sync(0xffffffffu, cnt, o);
            if (lane == 0) out[row0 + u] = (float)cnt + b0;
        }
    }

    // Tail rows (B not divisible by UNROLL; not hit for B = 131072).
    for (int row = nchunks * UNROLL + gw; row < B; row += nw) {
        const float4* xr = (const float4*)(x + (size_t)row * FDIM);
        float4 a = __ldcs(&xr[lane]);
        float4 b = __ldcs(&xr[lane + 32]);
        unsigned bits = pack_bits(a, b);
        unsigned xw[8];
#pragma unroll
        for (int w = 0; w < 8; w++)
            xw[w] = __ballot_sync(0xffffffffu, (bits >> w) & 1u);
        int cnt = 0;
#pragma unroll
        for (int k = 0; k < 4; k++) {
            int r = lane + 32 * k;
            unsigned acc = 0u;
#pragma unroll
            for (int w = 0; w < 8; w++)
                acc |= (xw[w] & s_care[w][r]) ^ s_pos[w][r];
            if (acc == 0u) cnt++;
        }
        for (int e = 0; e < nx; e++) {
            int r = s_xr[e];
            float s = 0.f;
#pragma unroll
            for (int w = 0; w < 8; w++) {
                if ((xw[w] >> lane) & 1u) {
                    int f = (w >> 2) * 128 + 4 * lane + (w & 3);
                    s += g_rw[r * FDIM + f];
                }
            }
#pragma unroll
            for (int o = 16; o; o >>= 1)
                s += __shfl_xor_sync(0xffffffffu, s, o);
            if (lane == 0 && s > g_thresh[r]) cnt++;
        }
#pragma unroll
        for (int o = 16; o; o >>= 1)
            cnt += __shfl_xor_sync(0xffffffffu, cnt, o);
        if (lane == 0) out[row] = (float)cnt + b0;
    }
}

extern "C" void kernel_launch(void* const* d_in, const int* in_sizes, int n_in,
                              void* d_out, int out_size) {
    const float* x  = (const float*)d_in[0];   // [B, 256] binary
    const float* wc = (const float*)d_in[1];   // [256]
    const float* wa = (const float*)d_in[2];   // [128, 256]
    const float* ba = (const float*)d_in[3];   // [128]
    const float* wo = (const float*)d_in[4];   // [1, 128]
    const float* bo = (const float*)d_in[5];   // [1]
    float* out = (float*)d_out;

    int B = in_sizes[0] / FDIM;

    prep_kernel<<<16, 256>>>(wc, wa, ba, wo);      // 128 warps, 1 per rule
    main_kernel<<<NBLOCKS, NTHREADS>>>(x, bo, out, B);
}

// round 8
// speedup vs baseline: 2.6285x; 1.9806x over previous
#include <cuda_runtime.h>

// R2Ntab: out[b] = (# rules r with h[b,r] > 0.999999) * [w_or>0] + b_or,
// h[b,r] = x_b . rw_r + b_and[r] - relu(rw_r).sum(), rw = w_and masked by
// w_cancel<0 columns. x binary {0,1} => pass <=> deficit(sum |w| over
// mismatched care features) < eps_r = b_and[r]-0.999999, which when
// |w| >= eps on all care features is EXACTLY the 256-bit pattern match
// (x_bits & care_r) == pos_r. Tiny weights -> don't-care if their total
// < eps, else that rule takes an exact fp32-dot fallback (expected: none).
//
// R8: CONTIGUOUS word layout: word w = features [32w, 32w+32), bit j =
// feature 32w+j. Word-0 reject (prob ~1-3e-5 per row) then needs only the
// row's FIRST 128 BYTES -> fast path reads 1 cache line per row instead of
// the whole 1KB row. DRAM traffic 134MB -> ~17MB (8x). Rows surviving
// word-0 load the remaining 896B on demand (correct for any data).

#define FDIM 256
#define RDIM 128
#define UNROLL 8
#define NTHREADS 256
#define NBLOCKS 592

__device__ unsigned g_pos[8][RDIM];
__device__ unsigned g_care[8][RDIM];
__device__ float    g_thresh[RDIM];
__device__ float    g_rw[RDIM * FDIM];
__device__ int      g_exact_flag[RDIM];

// ---------------------------------------------------------------------------
// Prep: one warp per rule. Word w bit j <-> feature 32w + j.
// ---------------------------------------------------------------------------
__global__ void prep_kernel(const float* __restrict__ wc,
                            const float* __restrict__ wa,
                            const float* __restrict__ ba,
                            const float* __restrict__ wo) {
    int gt   = blockIdx.x * blockDim.x + threadIdx.x;
    int r    = gt >> 5;
    int lane = gt & 31;
    if (r >= RDIM) return;

    float eps     = ba[r] - 0.999999f;
    bool  include = wo[r] > 0.0f;

    float relu_sum = 0.f, sum_tiny = 0.f;
    unsigned pos[8], care[8];
#pragma unroll
    for (int w = 0; w < 8; w++) {
        int   f  = 32 * w + lane;
        float wv = (wc[f] < 0.f) ? 0.f : wa[r * FDIM + f];
        g_rw[r * FDIM + f] = wv;
        relu_sum += fmaxf(wv, 0.f);
        float aw   = fabsf(wv);
        bool  must = (aw >= eps);
        if (!must) sum_tiny += aw;
        pos[w]  = __ballot_sync(0xffffffffu, must && (wv > 0.f));
        care[w] = __ballot_sync(0xffffffffu, must && (wv != 0.f));
    }
#pragma unroll
    for (int o = 16; o; o >>= 1) {
        relu_sum += __shfl_xor_sync(0xffffffffu, relu_sum, o);
        sum_tiny += __shfl_xor_sync(0xffffffffu, sum_tiny, o);
    }

    bool afalse = (!include) || (eps <= 0.f);
    bool exact  = (!afalse) && (sum_tiny >= eps);
    if (afalse || exact) {
#pragma unroll
        for (int w = 0; w < 8; w++) { pos[w] = 0u; care[w] = 0u; }
        pos[0] = 0xFFFFFFFFu;   // (x & 0) == 0xFFFFFFFF: never matches
    }
    if (lane == 0) {
        g_thresh[r]     = relu_sum - eps;
        g_exact_flag[r] = exact ? 1 : 0;
#pragma unroll
        for (int w = 0; w < 8; w++) { g_pos[w][r] = pos[w]; g_care[w][r] = care[w]; }
    }
}

// ---------------------------------------------------------------------------
// Main: warp per row. Fast path = 1 LDG.32 per lane (row's first 128B),
// 2 ballots, 4 LOP3/ISETP. Only word-0 survivors read the other 896B.
// ---------------------------------------------------------------------------
__global__ void __launch_bounds__(NTHREADS)
main_kernel(const float* __restrict__ x,
            const float* __restrict__ bor,
            float* __restrict__ out, int B) {
    __shared__ unsigned s_pos[8][RDIM];
    __shared__ unsigned s_care[8][RDIM];
    __shared__ int s_nx;
    __shared__ int s_xr[RDIM];

    const int tid = threadIdx.x;
    if (tid == 0) s_nx = 0;
    __syncthreads();
    for (int i = tid; i < 8 * RDIM; i += NTHREADS) {
        (&s_pos[0][0])[i]  = (&g_pos[0][0])[i];
        (&s_care[0][0])[i] = (&g_care[0][0])[i];
    }
    if (tid < RDIM && g_exact_flag[tid]) {
        int i = atomicAdd(&s_nx, 1);
        s_xr[i] = tid;
    }
    __syncthreads();

    const int   lane = tid & 31;
    const int   nx   = s_nx;
    const float b0   = bor[0];

    // Word-0 masks for this lane's 4 rules, register-resident.
    unsigned p0[4], c0[4];
#pragma unroll
    for (int k = 0; k < 4; k++) {
        p0[k] = s_pos[0][lane + 32 * k];
        c0[k] = s_care[0][lane + 32 * k];
    }

    const int gw = blockIdx.x * (NTHREADS >> 5) + (tid >> 5);
    const int nw = gridDim.x * (NTHREADS >> 5);
    const int nchunks = B / UNROLL;

    // Full (rare) evaluation of one row given xw0; loads words 1..7 on demand.
    auto full_row = [&](unsigned xw0, int row) {
        unsigned xw[8];
        xw[0] = xw0;
#pragma unroll
        for (int w = 1; w < 8; w++) {
            float v = __ldcs(x + (size_t)row * FDIM + 32 * w + lane);
            xw[w] = __ballot_sync(0xffffffffu, v > 0.5f);
        }
        int cnt = 0;
#pragma unroll
        for (int k = 0; k < 4; k++) {
            int r = lane + 32 * k;
            unsigned acc = (xw0 & c0[k]) ^ p0[k];
            if (acc == 0u) {
#pragma unroll
                for (int w = 1; w < 8; w++)
                    acc |= (xw[w] & s_care[w][r]) ^ s_pos[w][r];
                if (acc == 0u) cnt++;
            }
        }
        for (int e = 0; e < nx; e++) {             // exact fp32 fallback
            int r = s_xr[e];
            float s = 0.f;
#pragma unroll
            for (int w = 0; w < 8; w++) {
                if ((xw[w] >> lane) & 1u)
                    s += g_rw[r * FDIM + 32 * w + lane];
            }
#pragma unroll
            for (int o = 16; o; o >>= 1)
                s += __shfl_xor_sync(0xffffffffu, s, o);
            if (lane == 0 && s > g_thresh[r]) cnt++;
        }
#pragma unroll
        for (int o = 16; o; o >>= 1)
            cnt += __shfl_xor_sync(0xffffffffu, cnt, o);
        if (lane == 0) out[row] = (float)cnt + b0;
    };

    for (int ch = gw; ch < nchunks; ch += nw) {
        int row0 = ch * UNROLL;

        // 8 independent LDG.32 per lane: first 128B of each of 8 rows.
        float v[UNROLL];
#pragma unroll
        for (int u = 0; u < UNROLL; u++)
            v[u] = __ldcs(x + (size_t)(row0 + u) * FDIM + lane);

#pragma unroll
        for (int u = 0; u < UNROLL; u++) {
            unsigned xw0 = __ballot_sync(0xffffffffu, v[u] > 0.5f);
            bool cand = false;
#pragma unroll
            for (int k = 0; k < 4; k++)
                cand |= (((xw0 & c0[k]) ^ p0[k]) == 0u);
            unsigned any = __ballot_sync(0xffffffffu, cand);

            if (any == 0u && nx == 0) {            // warp-uniform, ~always
                if (lane == 0) out[row0 + u] = b0;
                continue;
            }
            full_row(xw0, row0 + u);               // rare: reads rest of row
        }
    }

    // Tail rows (B not divisible by UNROLL; not hit for B = 131072).
    for (int row = nchunks * UNROLL + gw; row < B; row += nw) {
        float v = __ldcs(x + (size_t)row * FDIM + lane);
        unsigned xw0 = __ballot_sync(0xffffffffu, v > 0.5f);
        full_row(xw0, row);
    }
}

extern "C" void kernel_launch(void* const* d_in, const int* in_sizes, int n_in,
                              void* d_out, int out_size) {
    const float* x  = (const float*)d_in[0];   // [B, 256] binary
    const float* wc = (const float*)d_in[1];   // [256]
    const float* wa = (const float*)d_in[2];   // [128, 256]
    const float* ba = (const float*)d_in[3];   // [128]
    const float* wo = (const float*)d_in[4];   // [1, 128]
    const float* bo = (const float*)d_in[5];   // [1]
    float* out = (float*)d_out;

    int B = in_sizes[0] / FDIM;

    prep_kernel<<<16, 256>>>(wc, wa, ba, wo);      // 128 warps, 1 per rule
    main_kernel<<<NBLOCKS, NTHREADS>>>(x, bo, out, B);
}